// round 13
// baseline (speedup 1.0000x reference)
#include <cuda_runtime.h>
#include <math.h>

#define BATCH 64
#define NPTS 1024
#define NT 64
#define PPT 16              // points per thread (NT*PPT == NPTS)
#define NWARPS 2
#define KMASK 0xFFFFFC00u   // top 22 bits of d2, low 10 bits = point index

// Scratch: sorted death values [2*BATCH][NPTS] (0..63 = gts, 64..127 = preds)
__device__ float g_deaths[2 * BATCH][NPTS];
__device__ float g_partial[BATCH];

#define PACK2(out, lo, hi) \
    asm("mov.b64 %0, {%1, %2};" : "=l"(out) : "f"(lo), "f"(hi))
#define UNPACK2(lo, hi, in) \
    asm("mov.b64 {%0, %1}, %2;" : "=f"(lo), "=f"(hi) : "l"(in))
#define FMA2(out, a, b, c) \
    asm("fma.rn.f32x2 %0, %1, %2, %3;" : "=l"(out) : "l"(a), "l"(b), "l"(c))

__global__ __launch_bounds__(NT, 1)
void prim_kernel(const float* __restrict__ gts, const float* __restrict__ preds) {
    const int cloud = blockIdx.x;  // 0..127
    const float* base = (cloud < BATCH ? gts : preds) + (size_t)(cloud & (BATCH - 1)) * NPTS * 3;

    __shared__ float raw[NPTS * 3];
    __shared__ float4 sp4[NPTS];                         // {x, y, z, |p|^2}
    __shared__ float sdeath[NPTS];                       // packed winner bits, then deaths
    __shared__ __align__(16) unsigned swarp[2][NWARPS];  // double-buffered per-warp argmin keys

    const int t = threadIdx.x;
    const int lane = t & 31;
    const int wid = t >> 5;

    // Coalesced load, then build float4-with-norm table.
    for (int i = t; i < NPTS * 3; i += NT) raw[i] = base[i];
    __syncthreads();
#pragma unroll
    for (int k = 0; k < PPT; k++) {
        const int i = t * PPT + k;
        const float x = raw[i * 3 + 0], y = raw[i * 3 + 1], z = raw[i * 3 + 2];
        sp4[i] = make_float4(x, y, z, fmaf(x, x, fmaf(y, y, z * z)));
    }
    __syncthreads();

    // Owned points: (-2x, -2y, -2z) packed as f32x2 pairs; |p|^2 and d2 scalar.
    unsigned long long mx2[PPT / 2], my2[PPT / 2], mz2[PPT / 2];
    float sq[PPT], d2[PPT];
    const unsigned idx0 = (unsigned)(t * PPT);
    const float4 p0 = sp4[0];
#pragma unroll
    for (int k = 0; k < PPT; k++) {
        const int i = t * PPT + k;
        const float4 p = sp4[i];
        sq[k] = p.w;
        // Gram form, matching the reference: d2 = |p|^2 + |p0|^2 - 2 p.p0, clamped >= 0
        const float dd = fmaf(-2.0f * p.x, p0.x,
                         fmaf(-2.0f * p.y, p0.y,
                         fmaf(-2.0f * p.z, p0.z, sq[k] + p0.w)));
        d2[k] = fmaxf(dd, 0.0f);
    }
#pragma unroll
    for (int p = 0; p < PPT / 2; p++) {
        const float4 a = sp4[t * PPT + 2 * p];
        const float4 b = sp4[t * PPT + 2 * p + 1];
        PACK2(mx2[p], -2.0f * a.x, -2.0f * b.x);
        PACK2(my2[p], -2.0f * a.y, -2.0f * b.y);
        PACK2(mz2[p], -2.0f * a.z, -2.0f * b.z);
    }
    if (t == 0) { d2[0] = 1e30f; sq[0] = 1e30f; }  // point 0 joined; sentinel self-propagates

    unsigned* const sbits = (unsigned*)sdeath;

#pragma unroll 2
    for (int it = 0; it < NPTS - 1; it++) {
        // Packed keys: top 22 bits of (non-negative) d2, low 10 bits = idx.
        // Positive-float bit order == float order -> unsigned min == quantized
        // argmin with lowest-index tie-breaking (== jnp.argmin).
        unsigned c[PPT];
#pragma unroll
        for (int k = 0; k < PPT; k++)
            c[k] = (__float_as_uint(d2[k]) & KMASK) | (idx0 + (unsigned)k);
        unsigned key = c[0];
#pragma unroll
        for (int k = 1; k < PPT; k++) key = min(key, c[k]);
        key = __reduce_min_sync(0xffffffffu, key);
        if (lane == 0) swarp[it & 1][wid] = key;
        __syncthreads();

        // Combine the 2 warp keys (one LDS.64 + 1 min).
        const uint2 a = *(const uint2*)&swarp[it & 1][0];
        const unsigned best = min(a.x, a.y);
        const int j = (int)(best & 1023u);
        if (t == 0) sbits[it] = best;   // sqrt deferred out of the loop

        const float4 pj = sp4[j];       // one LDS.128 broadcast
        const int rel = j - (int)idx0;

        // Broadcast pj into packed form (3 reg-pair builds).
        unsigned long long pjx2, pjy2, pjz2;
        PACK2(pjx2, pj.x, pj.x);
        PACK2(pjy2, pj.y, pj.y);
        PACK2(pjz2, pj.z, pj.z);
#pragma unroll
        for (int p = 0; p < PPT / 2; p++) {
            // nd = mx*pjx + my*pjy + mz*pjz + (sq + pjw), two points per chain.
            unsigned long long s2, acc;
            PACK2(s2, sq[2 * p] + pj.w, sq[2 * p + 1] + pj.w);
            FMA2(acc, mx2[p], pjx2, s2);
            FMA2(acc, my2[p], pjy2, acc);
            FMA2(acc, mz2[p], pjz2, acc);
            float lo, hi;
            UNPACK2(lo, hi, acc);
            // No clamp needed: cancellation error (~1e-6) << min true d2 (~1e-4),
            // so nd never goes negative on candidate minima.
            d2[2 * p]     = fminf(d2[2 * p],     lo);
            d2[2 * p + 1] = fminf(d2[2 * p + 1], hi);
        }
#pragma unroll
        for (int k = 0; k < PPT; k++)
            if (rel == k) { d2[k] = 1e30f; sq[k] = 1e30f; }
        // no second barrier: swarp is double-buffered
    }

    __syncthreads();
    // Convert packed winner bits -> death values (strip the 10 index bits).
    for (int i = t; i < NPTS - 1; i += NT) {
        const unsigned bits = sbits[i] & KMASK;
        sdeath[i] = sqrtf(__uint_as_float(bits) + 1e-12f);
    }
    if (t == 0) sdeath[NPTS - 1] = __int_as_float(0x7f800000);
    // Bitonic sort ascending.
    for (int k = 2; k <= NPTS; k <<= 1) {
        for (int j = k >> 1; j > 0; j >>= 1) {
            __syncthreads();
            for (int i = t; i < NPTS; i += NT) {
                const int ixj = i ^ j;
                if (ixj > i) {
                    const float va = sdeath[i];
                    const float vb = sdeath[ixj];
                    const bool up = ((i & k) == 0);
                    if ((va > vb) == up) { sdeath[i] = vb; sdeath[ixj] = va; }
                }
            }
        }
    }
    __syncthreads();
    for (int i = t; i < NPTS; i += NT) g_deaths[cloud][i] = sdeath[i];
}

// Per-batch partial sums (deterministic, no atomics).
__global__ void wloss_partial() {
    const int b = blockIdx.x;
    const int t = threadIdx.x;
    float s = 0.0f;
    for (int k = t; k < NPTS - 1; k += 256)
        s += fabsf(g_deaths[b][k] - g_deaths[BATCH + b][k]);
    __shared__ float red[8];
#pragma unroll
    for (int off = 16; off; off >>= 1) s += __shfl_down_sync(0xffffffffu, s, off);
    if ((t & 31) == 0) red[t >> 5] = s;
    __syncthreads();
    if (t < 32) {
        float v = (t < 8) ? red[t] : 0.0f;
#pragma unroll
        for (int off = 4; off; off >>= 1) v += __shfl_down_sync(0xffffffffu, v, off);
        if (t == 0) g_partial[b] = v;
    }
}

__global__ void wloss_final(float* __restrict__ out) {
    const int t = threadIdx.x;  // 32 threads
    float v = g_partial[t] + g_partial[t + 32];
#pragma unroll
    for (int off = 16; off; off >>= 1) v += __shfl_down_sync(0xffffffffu, v, off);
    if (t == 0) *out = v * (1.0f / BATCH);  // TOPO_LAMBDA = 1.0
}

extern "C" void kernel_launch(void* const* d_in, const int* in_sizes, int n_in,
                              void* d_out, int out_size) {
    const float* gts = (const float*)d_in[0];
    const float* preds = (const float*)d_in[1];
    float* out = (float*)d_out;
    prim_kernel<<<2 * BATCH, NT>>>(gts, preds);
    wloss_partial<<<BATCH, 256>>>();
    wloss_final<<<1, 32>>>(out);
}

// round 14
// speedup vs baseline: 1.5017x; 1.5017x over previous
#include <cuda_runtime.h>
#include <math.h>

#define BATCH 64
#define NPTS 1024
#define NT 128
#define PPT 8               // points per thread (NT*PPT == NPTS)
#define NWARPS 4
#define KMASK 0xFFFFFC00u   // top 22 bits of d2, low 10 bits = point index

// Scratch: sorted death values [2*BATCH][NPTS] (0..63 = gts, 64..127 = preds)
__device__ float g_deaths[2 * BATCH][NPTS];
__device__ float g_partial[BATCH];

#define PACK2(out, lo, hi) \
    asm("mov.b64 %0, {%1, %2};" : "=l"(out) : "f"(lo), "f"(hi))
#define UNPACK2(lo, hi, in) \
    asm("mov.b64 {%0, %1}, %2;" : "=f"(lo), "=f"(hi) : "l"(in))
#define FMA2(out, a, b, c) \
    asm("fma.rn.f32x2 %0, %1, %2, %3;" : "=l"(out) : "l"(a), "l"(b), "l"(c))
#define ADD2(out, a, b) \
    asm("add.rn.f32x2 %0, %1, %2;" : "=l"(out) : "l"(a), "l"(b))

union F2U { float2 f; unsigned long long u; };

__global__ __launch_bounds__(NT, 1)
void prim_kernel(const float* __restrict__ gts, const float* __restrict__ preds) {
    const int cloud = blockIdx.x;  // 0..127
    const float* base = (cloud < BATCH ? gts : preds) + (size_t)(cloud & (BATCH - 1)) * NPTS * 3;

    __shared__ float raw[NPTS * 3];
    __shared__ float4 sp4[NPTS];                         // {x, y, z, |p|^2}
    __shared__ float sdeath[NPTS];                       // packed winner bits, then deaths
    __shared__ __align__(16) unsigned swarp[2][NWARPS];  // double-buffered per-warp argmin keys

    const int t = threadIdx.x;
    const int lane = t & 31;
    const int wid = t >> 5;

    // Coalesced load, then build float4-with-norm table.
    for (int i = t; i < NPTS * 3; i += NT) raw[i] = base[i];
    __syncthreads();
#pragma unroll
    for (int k = 0; k < PPT; k++) {
        const int i = t * PPT + k;
        const float x = raw[i * 3 + 0], y = raw[i * 3 + 1], z = raw[i * 3 + 2];
        sp4[i] = make_float4(x, y, z, fmaf(x, x, fmaf(y, y, z * z)));
    }
    __syncthreads();

    // Owned points: (-2x, -2y, -2z) packed as f32x2 pairs; |p|^2 packed; d2 scalar.
    unsigned long long mx2[PPT / 2], my2[PPT / 2], mz2[PPT / 2];
    F2U sq2[PPT / 2];
    float d2[PPT];
    const unsigned idx0 = (unsigned)(t * PPT);
    const float4 p0 = sp4[0];
#pragma unroll
    for (int k = 0; k < PPT; k++) {
        const int i = t * PPT + k;
        const float4 p = sp4[i];
        // Gram form, matching the reference: d2 = |p|^2 + |p0|^2 - 2 p.p0, clamped >= 0
        const float dd = fmaf(-2.0f * p.x, p0.x,
                         fmaf(-2.0f * p.y, p0.y,
                         fmaf(-2.0f * p.z, p0.z, p.w + p0.w)));
        d2[k] = fmaxf(dd, 0.0f);
    }
#pragma unroll
    for (int p = 0; p < PPT / 2; p++) {
        const float4 a = sp4[t * PPT + 2 * p];
        const float4 b = sp4[t * PPT + 2 * p + 1];
        PACK2(mx2[p], -2.0f * a.x, -2.0f * b.x);
        PACK2(my2[p], -2.0f * a.y, -2.0f * b.y);
        PACK2(mz2[p], -2.0f * a.z, -2.0f * b.z);
        sq2[p].f = make_float2(a.w, b.w);
    }
    if (t == 0) { d2[0] = 1e30f; sq2[0].f.x = 1e30f; }  // point 0 joined; sentinel self-propagates

    unsigned* const sbits = (unsigned*)sdeath;

#pragma unroll 2
    for (int it = 0; it < NPTS - 1; it++) {
        // Packed keys: top 22 bits of (non-negative) d2, low 10 bits = idx.
        // Positive-float bit order == float order -> unsigned min == quantized
        // argmin with lowest-index tie-breaking (== jnp.argmin).
        unsigned c[PPT];
#pragma unroll
        for (int k = 0; k < PPT; k++)
            c[k] = (__float_as_uint(d2[k]) & KMASK) | (idx0 + (unsigned)k);
        unsigned key = min(min(min(c[0], c[1]), min(c[2], c[3])),
                           min(min(c[4], c[5]), min(c[6], c[7])));
        key = __reduce_min_sync(0xffffffffu, key);
        if (lane == 0) swarp[it & 1][wid] = key;
        __syncthreads();

        // All threads redundantly combine the 4 warp keys (1x LDS.128 + 3 mins).
        const uint4 a = *(const uint4*)&swarp[it & 1][0];
        const unsigned best = min(min(a.x, a.y), min(a.z, a.w));
        const int j = (int)(best & 1023u);
        if (t == 0) sbits[it] = best;   // sqrt deferred out of the loop

        const float4 pj = sp4[j];       // one LDS.128 broadcast
        const int rel = j - (int)idx0;

        // Broadcast pj into packed form.
        unsigned long long pjx2, pjy2, pjz2, pjw2;
        PACK2(pjx2, pj.x, pj.x);
        PACK2(pjy2, pj.y, pj.y);
        PACK2(pjz2, pj.z, pj.z);
        PACK2(pjw2, pj.w, pj.w);
#pragma unroll
        for (int p = 0; p < PPT / 2; p++) {
            // nd = mx*pjx + my*pjy + mz*pjz + (sq + pjw), two points per chain.
            unsigned long long s2, acc;
            ADD2(s2, sq2[p].u, pjw2);
            FMA2(acc, mx2[p], pjx2, s2);
            FMA2(acc, my2[p], pjy2, acc);
            FMA2(acc, mz2[p], pjz2, acc);
            float lo, hi;
            UNPACK2(lo, hi, acc);
            // No clamp needed: cancellation error (~1e-6) << min true d2 (~1e-4),
            // so nd never goes negative on candidate minima.
            d2[2 * p]     = fminf(d2[2 * p],     lo);
            d2[2 * p + 1] = fminf(d2[2 * p + 1], hi);
        }
        // Join: the ISETP predicates are shared between the d2 and sq selects.
#pragma unroll
        for (int p = 0; p < PPT / 2; p++) {
            if (rel == 2 * p)     { d2[2 * p]     = 1e30f; sq2[p].f.x = 1e30f; }
            if (rel == 2 * p + 1) { d2[2 * p + 1] = 1e30f; sq2[p].f.y = 1e30f; }
        }
        // no second barrier: swarp is double-buffered
    }

    __syncthreads();
    // Convert packed winner bits -> death values (strip the 10 index bits).
    for (int i = t; i < NPTS - 1; i += NT) {
        const unsigned bits = sbits[i] & KMASK;
        sdeath[i] = sqrtf(__uint_as_float(bits) + 1e-12f);
    }
    if (t == 0) sdeath[NPTS - 1] = __int_as_float(0x7f800000);
    // Bitonic sort ascending.
    for (int k = 2; k <= NPTS; k <<= 1) {
        for (int j = k >> 1; j > 0; j >>= 1) {
            __syncthreads();
            for (int i = t; i < NPTS; i += NT) {
                const int ixj = i ^ j;
                if (ixj > i) {
                    const float va = sdeath[i];
                    const float vb = sdeath[ixj];
                    const bool up = ((i & k) == 0);
                    if ((va > vb) == up) { sdeath[i] = vb; sdeath[ixj] = va; }
                }
            }
        }
    }
    __syncthreads();
    for (int i = t; i < NPTS; i += NT) g_deaths[cloud][i] = sdeath[i];
}

// Per-batch partial sums (deterministic, no atomics).
__global__ void wloss_partial() {
    const int b = blockIdx.x;
    const int t = threadIdx.x;
    float s = 0.0f;
    for (int k = t; k < NPTS - 1; k += 256)
        s += fabsf(g_deaths[b][k] - g_deaths[BATCH + b][k]);
    __shared__ float red[8];
#pragma unroll
    for (int off = 16; off; off >>= 1) s += __shfl_down_sync(0xffffffffu, s, off);
    if ((t & 31) == 0) red[t >> 5] = s;
    __syncthreads();
    if (t < 32) {
        float v = (t < 8) ? red[t] : 0.0f;
#pragma unroll
        for (int off = 4; off; off >>= 1) v += __shfl_down_sync(0xffffffffu, v, off);
        if (t == 0) g_partial[b] = v;
    }
}

__global__ void wloss_final(float* __restrict__ out) {
    const int t = threadIdx.x;  // 32 threads
    float v = g_partial[t] + g_partial[t + 32];
#pragma unroll
    for (int off = 16; off; off >>= 1) v += __shfl_down_sync(0xffffffffu, v, off);
    if (t == 0) *out = v * (1.0f / BATCH);  // TOPO_LAMBDA = 1.0
}

extern "C" void kernel_launch(void* const* d_in, const int* in_sizes, int n_in,
                              void* d_out, int out_size) {
    const float* gts = (const float*)d_in[0];
    const float* preds = (const float*)d_in[1];
    float* out = (float*)d_out;
    prim_kernel<<<2 * BATCH, NT>>>(gts, preds);
    wloss_partial<<<BATCH, 256>>>();
    wloss_final<<<1, 32>>>(out);
}